// round 1
// baseline (speedup 1.0000x reference)
#include <cuda_runtime.h>
#include <cuda_bf16.h>
#include <math.h>

// Problem constants
#define BATCH 2
#define TSEQ  4096
#define DIM   2048
#define NH    16
#define HD    128
#define M1    (BATCH*TSEQ)      // 8192
#define N_QKV (3*DIM)           // 6144

// ---------------- scratch (static device globals; no allocs allowed) ----------
__device__ float g_qkv[(size_t)M1 * N_QKV];          // [8192,6144]
__device__ float g_q[(size_t)BATCH*NH*TSEQ*HD];      // [bh][t][d]
__device__ float g_k[(size_t)BATCH*NH*TSEQ*HD];
__device__ float g_v[(size_t)BATCH*NH*TSEQ*HD];
__device__ float g_att[(size_t)M1 * DIM];            // [b*T+t][c]
__device__ float g_ctab[(size_t)TSEQ * HD];
__device__ float g_stab[(size_t)TSEQ * HD];

// ---------------- cos/sin table --------------------------------------------
__global__ void build_tab(float* __restrict__ ct, float* __restrict__ st) {
    int t = blockIdx.x;
    int j = threadIdx.x;          // 0..127
    int m = j & 63;
    // mimic reference fp32 rounding: inv_freq = 1/(10000^(m/64)) in fp32
    float base = (float)pow(10000.0, (double)m / 64.0);
    float invf = 1.0f / base;
    float ang = (float)t * invf;  // fp32 product like jax
    ct[t*HD + j] = cosf(ang);
    st[t*HD + j] = sinf(ang);
}

// ---------------- NT GEMM: C[M,N] = A[M,K] * B[N,K]^T ------------------------
// 128x128 tile, BK=16, 256 threads, 8x8 per thread
#define GBM 128
#define GBN 128
#define GBK 16

__global__ __launch_bounds__(256) void gemm_nt(
    const float* __restrict__ A, const float* __restrict__ B,
    float* __restrict__ C, int M, int N, int K)
{
    __shared__ float As[GBK][GBM + 4];   // [k][m], pad 4 -> row 528B (16B aligned)
    __shared__ float Bs[GBK][GBN + 4];

    int tid = threadIdx.x;
    int tm = tid >> 4;        // 0..15
    int tn = tid & 15;        // 0..15
    int m0 = blockIdx.y * GBM;
    int n0 = blockIdx.x * GBN;

    float acc[8][8];
#pragma unroll
    for (int i = 0; i < 8; i++)
#pragma unroll
        for (int j = 0; j < 8; j++) acc[i][j] = 0.f;

    for (int k0 = 0; k0 < K; k0 += GBK) {
#pragma unroll
        for (int e = 0; e < 2; e++) {
            int idx = tid + e * 256;        // 0..511  (512 float4 per tile)
            int r  = idx >> 2;              // 0..127
            int c4 = (idx & 3) << 2;        // 0,4,8,12
            float4 va = *(const float4*)(A + (size_t)(m0 + r) * K + k0 + c4);
            As[c4+0][r] = va.x; As[c4+1][r] = va.y;
            As[c4+2][r] = va.z; As[c4+3][r] = va.w;
            float4 vb = *(const float4*)(B + (size_t)(n0 + r) * K + k0 + c4);
            Bs[c4+0][r] = vb.x; Bs[c4+1][r] = vb.y;
            Bs[c4+2][r] = vb.z; Bs[c4+3][r] = vb.w;
        }
        __syncthreads();

#pragma unroll
        for (int k = 0; k < GBK; k++) {
            float a[8], b[8];
            float4 a0 = *(const float4*)(&As[k][tm*8]);
            float4 a1 = *(const float4*)(&As[k][tm*8+4]);
            float4 b0 = *(const float4*)(&Bs[k][tn*8]);
            float4 b1 = *(const float4*)(&Bs[k][tn*8+4]);
            a[0]=a0.x;a[1]=a0.y;a[2]=a0.z;a[3]=a0.w;a[4]=a1.x;a[5]=a1.y;a[6]=a1.z;a[7]=a1.w;
            b[0]=b0.x;b[1]=b0.y;b[2]=b0.z;b[3]=b0.w;b[4]=b1.x;b[5]=b1.y;b[6]=b1.z;b[7]=b1.w;
#pragma unroll
            for (int i = 0; i < 8; i++)
#pragma unroll
                for (int j = 0; j < 8; j++)
                    acc[i][j] += a[i] * b[j];
        }
        __syncthreads();
    }

#pragma unroll
    for (int i = 0; i < 8; i++) {
        size_t row = (size_t)(m0 + tm*8 + i) * N + n0 + tn*8;
        float4 o0 = make_float4(acc[i][0], acc[i][1], acc[i][2], acc[i][3]);
        float4 o1 = make_float4(acc[i][4], acc[i][5], acc[i][6], acc[i][7]);
        *(float4*)(C + row)     = o0;
        *(float4*)(C + row + 4) = o1;
    }
}

// ---------------- RoPE + head split ------------------------------------------
// qkv [b*T+t][6144] -> Q/K/V [b*NH+h][t][128], RoPE applied to Q,K
__global__ void rope_split(const float* __restrict__ qkv,
                           const float* __restrict__ ct, const float* __restrict__ st,
                           float* __restrict__ Qo, float* __restrict__ Ko,
                           float* __restrict__ Vo)
{
    int h  = blockIdx.x;          // 0..15
    int bt = blockIdx.y;          // 0..8191
    int j  = threadIdx.x;         // 0..127
    int b  = bt >> 12;
    int t  = bt & (TSEQ - 1);

    size_t base = (size_t)bt * N_QKV + h * HD;
    float c = ct[t*HD + j];
    float s = st[t*HD + j];

    float xq  = qkv[base + j];
    float xqp = qkv[base + (j ^ 1)];
    float rq  = (j & 1) ? xqp : -xqp;

    float xk  = qkv[base + DIM + j];
    float xkp = qkv[base + DIM + (j ^ 1)];
    float rk  = (j & 1) ? xkp : -xkp;

    float xv  = qkv[base + 2*DIM + j];

    size_t ob = ((size_t)(b*NH + h) * TSEQ + t) * HD + j;
    Qo[ob] = xq * c + rq * s;
    Ko[ob] = xk * c + rk * s;
    Vo[ob] = xv;
}

// ---------------- flash attention (fp32, causal) -----------------------------
#define FBQ 64
#define FBK 64
// smem floats: Qs 128*65 + Ks 128*65 + Vs 64*128 + Ss 64*65 + 192
#define FLASH_SMEM_FLOATS (128*65 + 128*65 + 64*128 + 64*65 + 192)
#define FLASH_SMEM_BYTES (FLASH_SMEM_FLOATS * 4)

__global__ __launch_bounds__(256) void flash_kernel(
    const float* __restrict__ Q, const float* __restrict__ K,
    const float* __restrict__ V, float* __restrict__ Oatt)
{
    extern __shared__ float fsm[];
    float* Qs  = fsm;                  // [128][65] transposed (d-major)
    float* Ks  = Qs + 128*65;          // [128][65]
    float* Vs  = Ks + 128*65;          // [64][128] row-major
    float* Ss  = Vs + 64*128;          // [64][65]
    float* m_s = Ss + 64*65;
    float* l_s = m_s + 64;
    float* al_s = l_s + 64;

    int qi = blockIdx.x;               // q tile 0..63
    int bh = blockIdx.y;               // 0..31
    int tid = threadIdx.x;
    int tm = tid >> 4;                 // 0..15
    int tn = tid & 15;                 // 0..15

    const float* Qp = Q + (size_t)bh * TSEQ * HD;
    const float* Kp = K + (size_t)bh * TSEQ * HD;
    const float* Vp = V + (size_t)bh * TSEQ * HD;

    int q0 = qi * FBQ;
    // load Q tile transposed into smem
#pragma unroll
    for (int e = 0; e < 8; e++) {
        int idx4 = tid + e * 256;       // 0..2047
        int r  = idx4 >> 5;             // 0..63
        int c4 = (idx4 & 31) << 2;      // 0..124
        float4 v = *(const float4*)(Qp + (size_t)(q0 + r) * HD + c4);
        Qs[(c4+0)*65 + r] = v.x; Qs[(c4+1)*65 + r] = v.y;
        Qs[(c4+2)*65 + r] = v.z; Qs[(c4+3)*65 + r] = v.w;
    }
    if (tid < 64) { m_s[tid] = -1e30f; l_s[tid] = 0.f; }

    float acc[4][8];
#pragma unroll
    for (int i = 0; i < 4; i++)
#pragma unroll
        for (int j = 0; j < 8; j++) acc[i][j] = 0.f;

    const float scale = 0.08838834764831845f;   // 1/sqrt(128)

    for (int kt = 0; kt <= qi; kt++) {
        __syncthreads();
        int k0 = kt * FBK;
#pragma unroll
        for (int e = 0; e < 8; e++) {
            int idx4 = tid + e * 256;
            int r  = idx4 >> 5;
            int c4 = (idx4 & 31) << 2;
            float4 kv = *(const float4*)(Kp + (size_t)(k0 + r) * HD + c4);
            Ks[(c4+0)*65 + r] = kv.x; Ks[(c4+1)*65 + r] = kv.y;
            Ks[(c4+2)*65 + r] = kv.z; Ks[(c4+3)*65 + r] = kv.w;
            float4 vv = *(const float4*)(Vp + (size_t)(k0 + r) * HD + c4);
            *(float4*)(Vs + r * HD + c4) = vv;
        }
        __syncthreads();

        // S = Q K^T   (4x4 per thread)
        float sreg[4][4];
#pragma unroll
        for (int i = 0; i < 4; i++)
#pragma unroll
            for (int j = 0; j < 4; j++) sreg[i][j] = 0.f;

#pragma unroll 4
        for (int dd = 0; dd < HD; dd++) {
            float qa[4], kb[4];
#pragma unroll
            for (int i = 0; i < 4; i++) qa[i] = Qs[dd*65 + tm*4 + i];
#pragma unroll
            for (int j = 0; j < 4; j++) kb[j] = Ks[dd*65 + tn*4 + j];
#pragma unroll
            for (int i = 0; i < 4; i++)
#pragma unroll
                for (int j = 0; j < 4; j++)
                    sreg[i][j] += qa[i] * kb[j];
        }
        bool diag = (kt == qi);
#pragma unroll
        for (int i = 0; i < 4; i++)
#pragma unroll
            for (int j = 0; j < 4; j++) {
                float v = sreg[i][j] * scale;
                if (diag && (tn*4 + j) > (tm*4 + i)) v = -1e30f;
                Ss[(tm*4 + i)*65 + tn*4 + j] = v;
            }
        __syncthreads();

        if (tid < 64) {
            float mo = m_s[tid];
            float mn = mo;
#pragma unroll 8
            for (int j = 0; j < FBK; j++) mn = fmaxf(mn, Ss[tid*65 + j]);
            float al = __expf(mo - mn);
            float sum = 0.f;
#pragma unroll 8
            for (int j = 0; j < FBK; j++) {
                float p = __expf(Ss[tid*65 + j] - mn);
                Ss[tid*65 + j] = p;
                sum += p;
            }
            m_s[tid] = mn;
            l_s[tid] = l_s[tid] * al + sum;
            al_s[tid] = al;
        }
        __syncthreads();

        // O = diag(alpha) O + P V   (4 rows x 8 cols per thread)
        float al[4];
#pragma unroll
        for (int i = 0; i < 4; i++) al[i] = al_s[tm*4 + i];
#pragma unroll
        for (int i = 0; i < 4; i++)
#pragma unroll
            for (int j = 0; j < 8; j++) acc[i][j] *= al[i];

#pragma unroll 2
        for (int kk = 0; kk < FBK; kk++) {
            float p[4];
#pragma unroll
            for (int i = 0; i < 4; i++) p[i] = Ss[(tm*4 + i)*65 + kk];
            float4 v0 = *(const float4*)(Vs + kk*HD + tn*8);
            float4 v1 = *(const float4*)(Vs + kk*HD + tn*8 + 4);
            float vv[8] = {v0.x, v0.y, v0.z, v0.w, v1.x, v1.y, v1.z, v1.w};
#pragma unroll
            for (int i = 0; i < 4; i++)
#pragma unroll
                for (int j = 0; j < 8; j++)
                    acc[i][j] += p[i] * vv[j];
        }
    }

    // epilogue: normalize, write to [b*T+t][h*128+d]
    int b = bh >> 4, h = bh & 15;
#pragma unroll
    for (int i = 0; i < 4; i++) {
        float inv = 1.0f / l_s[tm*4 + i];
        int row = q0 + tm*4 + i;
        size_t ob = ((size_t)(b*TSEQ + row)) * DIM + h*HD + tn*8;
        float4 o0 = make_float4(acc[i][0]*inv, acc[i][1]*inv, acc[i][2]*inv, acc[i][3]*inv);
        float4 o1 = make_float4(acc[i][4]*inv, acc[i][5]*inv, acc[i][6]*inv, acc[i][7]*inv);
        *(float4*)(Oatt + ob)     = o0;
        *(float4*)(Oatt + ob + 4) = o1;
    }
}

// ---------------- launch ------------------------------------------------------
extern "C" void kernel_launch(void* const* d_in, const int* in_sizes, int n_in,
                              void* d_out, int out_size) {
    const float* x      = (const float*)d_in[0];
    const float* w_qkv  = (const float*)d_in[1];
    const float* w_proj = (const float*)d_in[2];
    float* out = (float*)d_out;

    float *qkv, *q, *k, *v, *att, *ct, *st;
    cudaGetSymbolAddress((void**)&qkv, g_qkv);
    cudaGetSymbolAddress((void**)&q,   g_q);
    cudaGetSymbolAddress((void**)&k,   g_k);
    cudaGetSymbolAddress((void**)&v,   g_v);
    cudaGetSymbolAddress((void**)&att, g_att);
    cudaGetSymbolAddress((void**)&ct,  g_ctab);
    cudaGetSymbolAddress((void**)&st,  g_stab);

    build_tab<<<TSEQ, HD>>>(ct, st);

    gemm_nt<<<dim3(N_QKV/GBN, M1/GBM), 256>>>(x, w_qkv, qkv, M1, N_QKV, DIM);

    rope_split<<<dim3(NH, M1), HD>>>(qkv, ct, st, q, k, v);

    cudaFuncSetAttribute(flash_kernel, cudaFuncAttributeMaxDynamicSharedMemorySize,
                         FLASH_SMEM_BYTES);
    flash_kernel<<<dim3(TSEQ/FBQ, BATCH*NH), 256, FLASH_SMEM_BYTES>>>(q, k, v, att);

    gemm_nt<<<dim3(DIM/GBN, M1/GBM), 256>>>(att, w_proj, out, M1, DIM, DIM);
}

// round 3
// speedup vs baseline: 1.2647x; 1.2647x over previous
#include <cuda_runtime.h>
#include <cuda_bf16.h>
#include <math.h>
#include <stdint.h>

// Problem constants
#define BATCH 2
#define TSEQ  4096
#define DIM   2048
#define NH    16
#define HD    128
#define M1    (BATCH*TSEQ)      // 8192
#define N_QKV (3*DIM)           // 6144

// ---------------- scratch (static device globals; no allocs allowed) ----------
__device__ float g_qkv[(size_t)M1 * N_QKV];          // [8192,6144]
__device__ float g_q[(size_t)BATCH*NH*TSEQ*HD];      // [bh][t][d]
__device__ float g_k[(size_t)BATCH*NH*TSEQ*HD];
__device__ float g_v[(size_t)BATCH*NH*TSEQ*HD];
__device__ float g_att[(size_t)M1 * DIM];            // [b*T+t][c]
__device__ float g_ctab[(size_t)TSEQ * HD];
__device__ float g_stab[(size_t)TSEQ * HD];

// ---------------- helpers -----------------------------------------------------
__device__ __forceinline__ uint32_t f2tf32(float x) {
    uint32_t u;
    asm("cvt.rna.tf32.f32 %0, %1;" : "=r"(u) : "f"(x));
    return u;
}

__device__ __forceinline__ void mma_tf32(float* d, const uint32_t* a, const uint32_t* b) {
    asm volatile(
        "mma.sync.aligned.m16n8k8.row.col.f32.tf32.tf32.f32 "
        "{%0,%1,%2,%3}, {%4,%5,%6,%7}, {%8,%9}, {%0,%1,%2,%3};"
        : "+f"(d[0]), "+f"(d[1]), "+f"(d[2]), "+f"(d[3])
        : "r"(a[0]), "r"(a[1]), "r"(a[2]), "r"(a[3]), "r"(b[0]), "r"(b[1]));
}

// ---------------- cos/sin table --------------------------------------------
__global__ void build_tab(float* __restrict__ ct, float* __restrict__ st) {
    int t = blockIdx.x;
    int j = threadIdx.x;          // 0..127
    int m = j & 63;
    float base = (float)pow(10000.0, (double)m / 64.0);
    float invf = 1.0f / base;
    float ang = (float)t * invf;
    ct[t*HD + j] = cosf(ang);
    st[t*HD + j] = sinf(ang);
}

// ---------------- tf32 mma.sync NT GEMM: C[M,N] = A[M,K] * B[N,K]^T ----------
// 128x128 CTA tile, BK=16, 256 threads (8 warps, 2x4), warp tile 64x32.
#define BM 128
#define BN 128
#define BK 16
#define TSTR 17    // smem row stride (floats)

__global__ __launch_bounds__(256, 2) void gemm_mma(
    const float* __restrict__ A, const float* __restrict__ B,
    float* __restrict__ C, int M, int N, int K)
{
    __shared__ uint32_t As[2][BM][TSTR];
    __shared__ uint32_t Bs[2][BN][TSTR];

    int tid  = threadIdx.x;
    int wid  = tid >> 5, lane = tid & 31;
    int g    = lane >> 2, tg = lane & 3;
    int wm   = wid >> 2;             // 0..1
    int wn   = wid & 3;              // 0..3
    int m0   = blockIdx.y * BM;
    int n0   = blockIdx.x * BN;

    int lr  = tid >> 1;              // 0..127 (row within tile)
    int lc  = (tid & 1) * 8;         // 0 or 8

    float acc[4][4][4];
#pragma unroll
    for (int i = 0; i < 4; i++)
#pragma unroll
        for (int j = 0; j < 4; j++)
#pragma unroll
            for (int r = 0; r < 4; r++) acc[i][j][r] = 0.f;

    const int nch = K / BK;

    // stage loader
    auto load_stage = [&](int ch, int s) {
        const float* Ag = A + (size_t)(m0 + lr) * K + ch * BK + lc;
        const float* Bg = B + (size_t)(n0 + lr) * K + ch * BK + lc;
        float4 a0 = *(const float4*)(Ag);
        float4 a1 = *(const float4*)(Ag + 4);
        float4 b0 = *(const float4*)(Bg);
        float4 b1 = *(const float4*)(Bg + 4);
        uint32_t* ap = &As[s][lr][lc];
        ap[0] = f2tf32(a0.x); ap[1] = f2tf32(a0.y); ap[2] = f2tf32(a0.z); ap[3] = f2tf32(a0.w);
        ap[4] = f2tf32(a1.x); ap[5] = f2tf32(a1.y); ap[6] = f2tf32(a1.z); ap[7] = f2tf32(a1.w);
        uint32_t* bp = &Bs[s][lr][lc];
        bp[0] = f2tf32(b0.x); bp[1] = f2tf32(b0.y); bp[2] = f2tf32(b0.z); bp[3] = f2tf32(b0.w);
        bp[4] = f2tf32(b1.x); bp[5] = f2tf32(b1.y); bp[6] = f2tf32(b1.z); bp[7] = f2tf32(b1.w);
    };

    load_stage(0, 0);
    __syncthreads();

    for (int ch = 0; ch < nch; ch++) {
        int s = ch & 1;
        if (ch + 1 < nch) load_stage(ch + 1, s ^ 1);

#pragma unroll
        for (int ks = 0; ks < BK; ks += 8) {
            uint32_t afr[4][4];
#pragma unroll
            for (int mi = 0; mi < 4; mi++) {
                int mr = wm * 64 + mi * 16;
                afr[mi][0] = As[s][mr + g    ][ks + tg];
                afr[mi][1] = As[s][mr + g + 8][ks + tg];
                afr[mi][2] = As[s][mr + g    ][ks + tg + 4];
                afr[mi][3] = As[s][mr + g + 8][ks + tg + 4];
            }
            uint32_t bfr[4][2];
#pragma unroll
            for (int nj = 0; nj < 4; nj++) {
                int nr = wn * 32 + nj * 8;
                bfr[nj][0] = Bs[s][nr + g][ks + tg];
                bfr[nj][1] = Bs[s][nr + g][ks + tg + 4];
            }
#pragma unroll
            for (int mi = 0; mi < 4; mi++)
#pragma unroll
                for (int nj = 0; nj < 4; nj++)
                    mma_tf32(acc[mi][nj], afr[mi], bfr[nj]);
        }
        __syncthreads();
    }

    // epilogue: fragment layout -> global (float2 stores)
#pragma unroll
    for (int mi = 0; mi < 4; mi++) {
#pragma unroll
        for (int nj = 0; nj < 4; nj++) {
            int row = m0 + wm * 64 + mi * 16 + g;
            int col = n0 + wn * 32 + nj * 8 + tg * 2;
            *(float2*)(C + (size_t)row * N + col) =
                make_float2(acc[mi][nj][0], acc[mi][nj][1]);
            *(float2*)(C + (size_t)(row + 8) * N + col) =
                make_float2(acc[mi][nj][2], acc[mi][nj][3]);
        }
    }
}

// ---------------- RoPE + head split ------------------------------------------
__global__ void rope_split(const float* __restrict__ qkv,
                           const float* __restrict__ ct, const float* __restrict__ st,
                           float* __restrict__ Qo, float* __restrict__ Ko,
                           float* __restrict__ Vo)
{
    int h  = blockIdx.x;
    int bt = blockIdx.y;
    int j  = threadIdx.x;
    int b  = bt >> 12;
    int t  = bt & (TSEQ - 1);

    size_t base = (size_t)bt * N_QKV + h * HD;
    float c = ct[t*HD + j];
    float s = st[t*HD + j];

    float xq  = qkv[base + j];
    float xqp = qkv[base + (j ^ 1)];
    float rq  = (j & 1) ? xqp : -xqp;

    float xk  = qkv[base + DIM + j];
    float xkp = qkv[base + DIM + (j ^ 1)];
    float rk  = (j & 1) ? xkp : -xkp;

    float xv  = qkv[base + 2*DIM + j];

    size_t ob = ((size_t)(b*NH + h) * TSEQ + t) * HD + j;
    Qo[ob] = xq * c + rq * s;
    Ko[ob] = xk * c + rk * s;
    Vo[ob] = xv;
}

// ---------------- flash attention (fp32, causal) -----------------------------
#define FBQ 64
#define FBK 64
#define FLASH_SMEM_FLOATS (128*65 + 128*65 + 64*128 + 64*65 + 192)
#define FLASH_SMEM_BYTES (FLASH_SMEM_FLOATS * 4)

__global__ __launch_bounds__(256) void flash_kernel(
    const float* __restrict__ Q, const float* __restrict__ K,
    const float* __restrict__ V, float* __restrict__ Oatt)
{
    extern __shared__ float fsm[];
    float* Qs  = fsm;
    float* Ks  = Qs + 128*65;
    float* Vs  = Ks + 128*65;
    float* Ss  = Vs + 64*128;
    float* m_s = Ss + 64*65;
    float* l_s = m_s + 64;
    float* al_s = l_s + 64;

    int qi = blockIdx.x;
    int bh = blockIdx.y;
    int tid = threadIdx.x;
    int tm = tid >> 4;
    int tn = tid & 15;

    const float* Qp = Q + (size_t)bh * TSEQ * HD;
    const float* Kp = K + (size_t)bh * TSEQ * HD;
    const float* Vp = V + (size_t)bh * TSEQ * HD;

    int q0 = qi * FBQ;
#pragma unroll
    for (int e = 0; e < 8; e++) {
        int idx4 = tid + e * 256;
        int r  = idx4 >> 5;
        int c4 = (idx4 & 31) << 2;
        float4 v = *(const float4*)(Qp + (size_t)(q0 + r) * HD + c4);
        Qs[(c4+0)*65 + r] = v.x; Qs[(c4+1)*65 + r] = v.y;
        Qs[(c4+2)*65 + r] = v.z; Qs[(c4+3)*65 + r] = v.w;
    }
    if (tid < 64) { m_s[tid] = -1e30f; l_s[tid] = 0.f; }

    float acc[4][8];
#pragma unroll
    for (int i = 0; i < 4; i++)
#pragma unroll
        for (int j = 0; j < 8; j++) acc[i][j] = 0.f;

    const float scale = 0.08838834764831845f;

    for (int kt = 0; kt <= qi; kt++) {
        __syncthreads();
        int k0 = kt * FBK;
#pragma unroll
        for (int e = 0; e < 8; e++) {
            int idx4 = tid + e * 256;
            int r  = idx4 >> 5;
            int c4 = (idx4 & 31) << 2;
            float4 kv = *(const float4*)(Kp + (size_t)(k0 + r) * HD + c4);
            Ks[(c4+0)*65 + r] = kv.x; Ks[(c4+1)*65 + r] = kv.y;
            Ks[(c4+2)*65 + r] = kv.z; Ks[(c4+3)*65 + r] = kv.w;
            float4 vv = *(const float4*)(Vp + (size_t)(k0 + r) * HD + c4);
            *(float4*)(Vs + r * HD + c4) = vv;
        }
        __syncthreads();

        float sreg[4][4];
#pragma unroll
        for (int i = 0; i < 4; i++)
#pragma unroll
            for (int j = 0; j < 4; j++) sreg[i][j] = 0.f;

#pragma unroll 4
        for (int dd = 0; dd < HD; dd++) {
            float qa[4], kb[4];
#pragma unroll
            for (int i = 0; i < 4; i++) qa[i] = Qs[dd*65 + tm*4 + i];
#pragma unroll
            for (int j = 0; j < 4; j++) kb[j] = Ks[dd*65 + tn*4 + j];
#pragma unroll
            for (int i = 0; i < 4; i++)
#pragma unroll
                for (int j = 0; j < 4; j++)
                    sreg[i][j] += qa[i] * kb[j];
        }
        bool diag = (kt == qi);
#pragma unroll
        for (int i = 0; i < 4; i++)
#pragma unroll
            for (int j = 0; j < 4; j++) {
                float v = sreg[i][j] * scale;
                if (diag && (tn*4 + j) > (tm*4 + i)) v = -1e30f;
                Ss[(tm*4 + i)*65 + tn*4 + j] = v;
            }
        __syncthreads();

        if (tid < 64) {
            float mo = m_s[tid];
            float mn = mo;
#pragma unroll 8
            for (int j = 0; j < FBK; j++) mn = fmaxf(mn, Ss[tid*65 + j]);
            float al = __expf(mo - mn);
            float sum = 0.f;
#pragma unroll 8
            for (int j = 0; j < FBK; j++) {
                float p = __expf(Ss[tid*65 + j] - mn);
                Ss[tid*65 + j] = p;
                sum += p;
            }
            m_s[tid] = mn;
            l_s[tid] = l_s[tid] * al + sum;
            al_s[tid] = al;
        }
        __syncthreads();

        float al[4];
#pragma unroll
        for (int i = 0; i < 4; i++) al[i] = al_s[tm*4 + i];
#pragma unroll
        for (int i = 0; i < 4; i++)
#pragma unroll
            for (int j = 0; j < 8; j++) acc[i][j] *= al[i];

#pragma unroll 2
        for (int kk = 0; kk < FBK; kk++) {
            float p[4];
#pragma unroll
            for (int i = 0; i < 4; i++) p[i] = Ss[(tm*4 + i)*65 + kk];
            float4 v0 = *(const float4*)(Vs + kk*HD + tn*8);
            float4 v1 = *(const float4*)(Vs + kk*HD + tn*8 + 4);
            float vv[8] = {v0.x, v0.y, v0.z, v0.w, v1.x, v1.y, v1.z, v1.w};
#pragma unroll
            for (int i = 0; i < 4; i++)
#pragma unroll
                for (int j = 0; j < 8; j++)
                    acc[i][j] += p[i] * vv[j];
        }
    }

    int b = bh >> 4, h = bh & 15;
#pragma unroll
    for (int i = 0; i < 4; i++) {
        float inv = 1.0f / l_s[tm*4 + i];
        int row = q0 + tm*4 + i;
        size_t ob = ((size_t)(b*TSEQ + row)) * DIM + h*HD + tn*8;
        float4 o0 = make_float4(acc[i][0]*inv, acc[i][1]*inv, acc[i][2]*inv, acc[i][3]*inv);
        float4 o1 = make_float4(acc[i][4]*inv, acc[i][5]*inv, acc[i][6]*inv, acc[i][7]*inv);
        *(float4*)(Oatt + ob)     = o0;
        *(float4*)(Oatt + ob + 4) = o1;
    }
}

// ---------------- launch ------------------------------------------------------
extern "C" void kernel_launch(void* const* d_in, const int* in_sizes, int n_in,
                              void* d_out, int out_size) {
    const float* x      = (const float*)d_in[0];
    const float* w_qkv  = (const float*)d_in[1];
    const float* w_proj = (const float*)d_in[2];
    float* out = (float*)d_out;

    float *qkv, *q, *k, *v, *att, *ct, *st;
    cudaGetSymbolAddress((void**)&qkv, g_qkv);
    cudaGetSymbolAddress((void**)&q,   g_q);
    cudaGetSymbolAddress((void**)&k,   g_k);
    cudaGetSymbolAddress((void**)&v,   g_v);
    cudaGetSymbolAddress((void**)&att, g_att);
    cudaGetSymbolAddress((void**)&ct,  g_ctab);
    cudaGetSymbolAddress((void**)&st,  g_stab);

    cudaFuncSetAttribute(flash_kernel, cudaFuncAttributeMaxDynamicSharedMemorySize,
                         FLASH_SMEM_BYTES);

    build_tab<<<TSEQ, HD>>>(ct, st);

    gemm_mma<<<dim3(N_QKV/BN, M1/BM), 256>>>(x, w_qkv, qkv, M1, N_QKV, DIM);

    rope_split<<<dim3(NH, M1), HD>>>(qkv, ct, st, q, k, v);

    flash_kernel<<<dim3(TSEQ/FBQ, BATCH*NH), 256, FLASH_SMEM_BYTES>>>(q, k, v, att);

    gemm_mma<<<dim3(DIM/BN, M1/BM), 256>>>(att, w_proj, out, M1, DIM, DIM);
}

// round 4
// speedup vs baseline: 2.5282x; 1.9991x over previous
#include <cuda_runtime.h>
#include <cuda_bf16.h>
#include <math.h>
#include <stdint.h>

// Problem constants
#define BATCH 2
#define TSEQ  4096
#define DIM   2048
#define NH    16
#define HD    128
#define M1    (BATCH*TSEQ)      // 8192
#define N_QKV (3*DIM)           // 6144

// ---------------- scratch (static device globals; no allocs allowed) ----------
__device__ float g_qkv[(size_t)M1 * N_QKV];          // [8192,6144]
__device__ float g_q[(size_t)BATCH*NH*TSEQ*HD];      // [bh][t][d]
__device__ float g_k[(size_t)BATCH*NH*TSEQ*HD];
__device__ float g_v[(size_t)BATCH*NH*TSEQ*HD];
__device__ float g_att[(size_t)M1 * DIM];            // [b*T+t][c]
__device__ float g_ctab[(size_t)TSEQ * HD];
__device__ float g_stab[(size_t)TSEQ * HD];

// ---------------- helpers -----------------------------------------------------
__device__ __forceinline__ uint32_t f2tf32(float x) {
    uint32_t u;
    asm("cvt.rna.tf32.f32 %0, %1;" : "=r"(u) : "f"(x));
    return u;
}

__device__ __forceinline__ void mma_tf32(float* d, const uint32_t* a, const uint32_t* b) {
    asm volatile(
        "mma.sync.aligned.m16n8k8.row.col.f32.tf32.tf32.f32 "
        "{%0,%1,%2,%3}, {%4,%5,%6,%7}, {%8,%9}, {%0,%1,%2,%3};"
        : "+f"(d[0]), "+f"(d[1]), "+f"(d[2]), "+f"(d[3])
        : "r"(a[0]), "r"(a[1]), "r"(a[2]), "r"(a[3]), "r"(b[0]), "r"(b[1]));
}

// ---------------- cos/sin table --------------------------------------------
__global__ void build_tab(float* __restrict__ ct, float* __restrict__ st) {
    int t = blockIdx.x;
    int j = threadIdx.x;          // 0..127
    int m = j & 63;
    float base = (float)pow(10000.0, (double)m / 64.0);
    float invf = 1.0f / base;
    float ang = (float)t * invf;
    ct[t*HD + j] = cosf(ang);
    st[t*HD + j] = sinf(ang);
}

// ---------------- tf32 mma.sync NT GEMM: C[M,N] = A[M,K] * B[N,K]^T ----------
#define BM 128
#define BN 128
#define BK 16
#define TSTR 17

__global__ __launch_bounds__(256, 2) void gemm_mma(
    const float* __restrict__ A, const float* __restrict__ B,
    float* __restrict__ C, int M, int N, int K)
{
    __shared__ uint32_t As[2][BM][TSTR];
    __shared__ uint32_t Bs[2][BN][TSTR];

    int tid  = threadIdx.x;
    int wid  = tid >> 5, lane = tid & 31;
    int g    = lane >> 2, tg = lane & 3;
    int wm   = wid >> 2;
    int wn   = wid & 3;
    int m0   = blockIdx.y * BM;
    int n0   = blockIdx.x * BN;

    int lr  = tid >> 1;
    int lc  = (tid & 1) * 8;

    float acc[4][4][4];
#pragma unroll
    for (int i = 0; i < 4; i++)
#pragma unroll
        for (int j = 0; j < 4; j++)
#pragma unroll
            for (int r = 0; r < 4; r++) acc[i][j][r] = 0.f;

    const int nch = K / BK;

    auto load_stage = [&](int ch, int s) {
        const float* Ag = A + (size_t)(m0 + lr) * K + ch * BK + lc;
        const float* Bg = B + (size_t)(n0 + lr) * K + ch * BK + lc;
        float4 a0 = *(const float4*)(Ag);
        float4 a1 = *(const float4*)(Ag + 4);
        float4 b0 = *(const float4*)(Bg);
        float4 b1 = *(const float4*)(Bg + 4);
        uint32_t* ap = &As[s][lr][lc];
        ap[0] = f2tf32(a0.x); ap[1] = f2tf32(a0.y); ap[2] = f2tf32(a0.z); ap[3] = f2tf32(a0.w);
        ap[4] = f2tf32(a1.x); ap[5] = f2tf32(a1.y); ap[6] = f2tf32(a1.z); ap[7] = f2tf32(a1.w);
        uint32_t* bp = &Bs[s][lr][lc];
        bp[0] = f2tf32(b0.x); bp[1] = f2tf32(b0.y); bp[2] = f2tf32(b0.z); bp[3] = f2tf32(b0.w);
        bp[4] = f2tf32(b1.x); bp[5] = f2tf32(b1.y); bp[6] = f2tf32(b1.z); bp[7] = f2tf32(b1.w);
    };

    load_stage(0, 0);
    __syncthreads();

    for (int ch = 0; ch < nch; ch++) {
        int s = ch & 1;
        if (ch + 1 < nch) load_stage(ch + 1, s ^ 1);

#pragma unroll
        for (int ks = 0; ks < BK; ks += 8) {
            uint32_t afr[4][4];
#pragma unroll
            for (int mi = 0; mi < 4; mi++) {
                int mr = wm * 64 + mi * 16;
                afr[mi][0] = As[s][mr + g    ][ks + tg];
                afr[mi][1] = As[s][mr + g + 8][ks + tg];
                afr[mi][2] = As[s][mr + g    ][ks + tg + 4];
                afr[mi][3] = As[s][mr + g + 8][ks + tg + 4];
            }
            uint32_t bfr[4][2];
#pragma unroll
            for (int nj = 0; nj < 4; nj++) {
                int nr = wn * 32 + nj * 8;
                bfr[nj][0] = Bs[s][nr + g][ks + tg];
                bfr[nj][1] = Bs[s][nr + g][ks + tg + 4];
            }
#pragma unroll
            for (int mi = 0; mi < 4; mi++)
#pragma unroll
                for (int nj = 0; nj < 4; nj++)
                    mma_tf32(acc[mi][nj], afr[mi], bfr[nj]);
        }
        __syncthreads();
    }

#pragma unroll
    for (int mi = 0; mi < 4; mi++) {
#pragma unroll
        for (int nj = 0; nj < 4; nj++) {
            int row = m0 + wm * 64 + mi * 16 + g;
            int col = n0 + wn * 32 + nj * 8 + tg * 2;
            *(float2*)(C + (size_t)row * N + col) =
                make_float2(acc[mi][nj][0], acc[mi][nj][1]);
            *(float2*)(C + (size_t)(row + 8) * N + col) =
                make_float2(acc[mi][nj][2], acc[mi][nj][3]);
        }
    }
}

// ---------------- RoPE + head split ------------------------------------------
__global__ void rope_split(const float* __restrict__ qkv,
                           const float* __restrict__ ct, const float* __restrict__ st,
                           float* __restrict__ Qo, float* __restrict__ Ko,
                           float* __restrict__ Vo)
{
    int h  = blockIdx.x;
    int bt = blockIdx.y;
    int j  = threadIdx.x;
    int b  = bt >> 12;
    int t  = bt & (TSEQ - 1);

    size_t base = (size_t)bt * N_QKV + h * HD;
    float c = ct[t*HD + j];
    float s = st[t*HD + j];

    float xq  = qkv[base + j];
    float xqp = qkv[base + (j ^ 1)];
    float rq  = (j & 1) ? xqp : -xqp;

    float xk  = qkv[base + DIM + j];
    float xkp = qkv[base + DIM + (j ^ 1)];
    float rk  = (j & 1) ? xkp : -xkp;

    float xv  = qkv[base + 2*DIM + j];

    size_t ob = ((size_t)(b*NH + h) * TSEQ + t) * HD + j;
    Qo[ob] = xq * c + rq * s;
    Ko[ob] = xk * c + rk * s;
    Vo[ob] = xv;
}

// ---------------- tf32 mma flash attention (causal) --------------------------
// Q tile 128, K tile 64, 8 warps, warp = 16 Q rows x full K width.
#define FQ 128
#define FK 64
#define QSTR 132
#define KSTR 132
#define VSTR 136
#define PSTR 68
#define OFF_Q 0
#define OFF_K (OFF_Q + FQ*QSTR)          // 16896
#define OFF_V (OFF_K + FK*KSTR)          // 25344
#define OFF_P (OFF_V + FK*VSTR)          // 34048
#define FLASH2_FLOATS (OFF_P + FQ*PSTR)  // 42752
#define FLASH2_BYTES (FLASH2_FLOATS * 4) // 171008

__global__ __launch_bounds__(256, 1) void flash_mma(
    const float* __restrict__ Q, const float* __restrict__ K,
    const float* __restrict__ V, float* __restrict__ Oatt)
{
    extern __shared__ float sm[];
    float* Qs = sm + OFF_Q;
    float* Ks = sm + OFF_K;
    float* Vs = sm + OFF_V;
    float* Ps = sm + OFF_P;

    int qi  = blockIdx.x;
    int bh  = blockIdx.y;
    int tid = threadIdx.x;
    int w    = tid >> 5;
    int lane = tid & 31;
    int g    = lane >> 2;
    int tg   = lane & 3;

    const float* Qp = Q + (size_t)bh * TSEQ * HD;
    const float* Kp = K + (size_t)bh * TSEQ * HD;
    const float* Vp = V + (size_t)bh * TSEQ * HD;

    int q0 = qi * FQ;

    // load Q tile (tf32-converted)
#pragma unroll
    for (int e = 0; e < 16; e++) {
        int idx = tid + e * 256;           // 0..4095 float4s
        int r  = idx >> 5;
        int c4 = (idx & 31) << 2;
        float4 v = *(const float4*)(Qp + (size_t)(q0 + r) * HD + c4);
        float4 o;
        o.x = __uint_as_float(f2tf32(v.x)); o.y = __uint_as_float(f2tf32(v.y));
        o.z = __uint_as_float(f2tf32(v.z)); o.w = __uint_as_float(f2tf32(v.w));
        *(float4*)(Qs + r * QSTR + c4) = o;
    }

    float o[16][4];
#pragma unroll
    for (int i = 0; i < 16; i++)
#pragma unroll
        for (int j = 0; j < 4; j++) o[i][j] = 0.f;

    float m0r = -1e30f, m1r = -1e30f;
    float l0 = 0.f, l1 = 0.f;
    const float scale = 0.08838834764831845f;   // 1/sqrt(128)

    int rowbase = q0 + w * 16;
    int r0g = rowbase + g;
    int r1g = rowbase + g + 8;

    int nkt = 2 * qi + 2;
    for (int kt = 0; kt < nkt; kt++) {
        int k0 = kt * FK;
        __syncthreads();
        // load K and V tiles (tf32-converted)
#pragma unroll
        for (int e = 0; e < 8; e++) {
            int idx = tid + e * 256;        // 0..2047 float4s
            int r  = idx >> 5;
            int c4 = (idx & 31) << 2;
            float4 kv = *(const float4*)(Kp + (size_t)(k0 + r) * HD + c4);
            float4 ko;
            ko.x = __uint_as_float(f2tf32(kv.x)); ko.y = __uint_as_float(f2tf32(kv.y));
            ko.z = __uint_as_float(f2tf32(kv.z)); ko.w = __uint_as_float(f2tf32(kv.w));
            *(float4*)(Ks + r * KSTR + c4) = ko;
            float4 vv = *(const float4*)(Vp + (size_t)(k0 + r) * HD + c4);
            float4 vo;
            vo.x = __uint_as_float(f2tf32(vv.x)); vo.y = __uint_as_float(f2tf32(vv.y));
            vo.z = __uint_as_float(f2tf32(vv.z)); vo.w = __uint_as_float(f2tf32(vv.w));
            *(float4*)(Vs + r * VSTR + c4) = vo;
        }
        __syncthreads();

        if (k0 > rowbase + 15) continue;    // fully masked for this warp

        // ---- S = Q K^T : warp tile 16 x 64 ----
        float s[8][4];
#pragma unroll
        for (int nj = 0; nj < 8; nj++)
#pragma unroll
            for (int r = 0; r < 4; r++) s[nj][r] = 0.f;

#pragma unroll
        for (int ks = 0; ks < 16; ks++) {
            uint32_t a[4];
            a[0] = __float_as_uint(Qs[(rowbase - q0 + g    ) * QSTR + ks*8 + tg]);
            a[1] = __float_as_uint(Qs[(rowbase - q0 + g + 8) * QSTR + ks*8 + tg]);
            a[2] = __float_as_uint(Qs[(rowbase - q0 + g    ) * QSTR + ks*8 + tg + 4]);
            a[3] = __float_as_uint(Qs[(rowbase - q0 + g + 8) * QSTR + ks*8 + tg + 4]);
#pragma unroll
            for (int nj = 0; nj < 8; nj++) {
                uint32_t b[2];
                b[0] = __float_as_uint(Ks[(nj*8 + g) * KSTR + ks*8 + tg]);
                b[1] = __float_as_uint(Ks[(nj*8 + g) * KSTR + ks*8 + tg + 4]);
                mma_tf32(s[nj], a, b);
            }
        }

        // ---- causal mask ----
        if (k0 + FK - 1 > rowbase) {
#pragma unroll
            for (int nj = 0; nj < 8; nj++) {
                int c = k0 + nj*8 + 2*tg;
                if (c     > r0g) s[nj][0] = -1e30f;
                if (c + 1 > r0g) s[nj][1] = -1e30f;
                if (c     > r1g) s[nj][2] = -1e30f;
                if (c + 1 > r1g) s[nj][3] = -1e30f;
            }
        }

        // ---- online softmax (warp-local, quad reductions) ----
        float mx0 = -1e30f, mx1 = -1e30f;
#pragma unroll
        for (int nj = 0; nj < 8; nj++) {
            mx0 = fmaxf(mx0, fmaxf(s[nj][0], s[nj][1]));
            mx1 = fmaxf(mx1, fmaxf(s[nj][2], s[nj][3]));
        }
        mx0 = fmaxf(mx0, __shfl_xor_sync(0xffffffff, mx0, 1));
        mx0 = fmaxf(mx0, __shfl_xor_sync(0xffffffff, mx0, 2));
        mx1 = fmaxf(mx1, __shfl_xor_sync(0xffffffff, mx1, 1));
        mx1 = fmaxf(mx1, __shfl_xor_sync(0xffffffff, mx1, 2));

        float mn0 = fmaxf(m0r, mx0);
        float mn1 = fmaxf(m1r, mx1);
        float al0 = __expf((m0r - mn0) * scale);
        float al1 = __expf((m1r - mn1) * scale);
        m0r = mn0; m1r = mn1;

        float sum0 = 0.f, sum1 = 0.f;
#pragma unroll
        for (int nj = 0; nj < 8; nj++) {
            float p0 = __expf((s[nj][0] - mn0) * scale);
            float p1 = __expf((s[nj][1] - mn0) * scale);
            float p2 = __expf((s[nj][2] - mn1) * scale);
            float p3 = __expf((s[nj][3] - mn1) * scale);
            s[nj][0] = p0; s[nj][1] = p1; s[nj][2] = p2; s[nj][3] = p3;
            sum0 += p0 + p1; sum1 += p2 + p3;
        }
        sum0 += __shfl_xor_sync(0xffffffff, sum0, 1);
        sum0 += __shfl_xor_sync(0xffffffff, sum0, 2);
        sum1 += __shfl_xor_sync(0xffffffff, sum1, 1);
        sum1 += __shfl_xor_sync(0xffffffff, sum1, 2);

        l0 = l0 * al0 + sum0;
        l1 = l1 * al1 + sum1;

#pragma unroll
        for (int t2 = 0; t2 < 16; t2++) {
            o[t2][0] *= al0; o[t2][1] *= al0;
            o[t2][2] *= al1; o[t2][3] *= al1;
        }

        // ---- write P to warp-private smem (tf32) ----
        int pr0 = (rowbase - q0 + g) * PSTR;
        int pr1 = (rowbase - q0 + g + 8) * PSTR;
#pragma unroll
        for (int nj = 0; nj < 8; nj++) {
            int c = nj*8 + 2*tg;
            Ps[pr0 + c    ] = __uint_as_float(f2tf32(s[nj][0]));
            Ps[pr0 + c + 1] = __uint_as_float(f2tf32(s[nj][1]));
            Ps[pr1 + c    ] = __uint_as_float(f2tf32(s[nj][2]));
            Ps[pr1 + c + 1] = __uint_as_float(f2tf32(s[nj][3]));
        }
        __syncwarp();

        // ---- O += P V : warp tile 16 x 128, K-dim 64 ----
#pragma unroll
        for (int ks2 = 0; ks2 < 8; ks2++) {
            uint32_t a2[4];
            a2[0] = __float_as_uint(Ps[pr0 + ks2*8 + tg]);
            a2[1] = __float_as_uint(Ps[pr1 + ks2*8 + tg]);
            a2[2] = __float_as_uint(Ps[pr0 + ks2*8 + tg + 4]);
            a2[3] = __float_as_uint(Ps[pr1 + ks2*8 + tg + 4]);
#pragma unroll
            for (int nj2 = 0; nj2 < 16; nj2++) {
                uint32_t b2[2];
                b2[0] = __float_as_uint(Vs[(ks2*8 + tg    ) * VSTR + nj2*8 + g]);
                b2[1] = __float_as_uint(Vs[(ks2*8 + tg + 4) * VSTR + nj2*8 + g]);
                mma_tf32(o[nj2], a2, b2);
            }
        }
        __syncwarp();
    }

    // ---- epilogue: normalize + write [b*T+row][h*128+d] ----
    float inv0 = 1.0f / l0;
    float inv1 = 1.0f / l1;
    int b = bh >> 4, h = bh & 15;
#pragma unroll
    for (int nj2 = 0; nj2 < 16; nj2++) {
        int col = h * HD + nj2*8 + 2*tg;
        *(float2*)(Oatt + (size_t)(b*TSEQ + r0g) * DIM + col) =
            make_float2(o[nj2][0] * inv0, o[nj2][1] * inv0);
        *(float2*)(Oatt + (size_t)(b*TSEQ + r1g) * DIM + col) =
            make_float2(o[nj2][2] * inv1, o[nj2][3] * inv1);
    }
}

// ---------------- launch ------------------------------------------------------
extern "C" void kernel_launch(void* const* d_in, const int* in_sizes, int n_in,
                              void* d_out, int out_size) {
    const float* x      = (const float*)d_in[0];
    const float* w_qkv  = (const float*)d_in[1];
    const float* w_proj = (const float*)d_in[2];
    float* out = (float*)d_out;

    float *qkv, *q, *k, *v, *att, *ct, *st;
    cudaGetSymbolAddress((void**)&qkv, g_qkv);
    cudaGetSymbolAddress((void**)&q,   g_q);
    cudaGetSymbolAddress((void**)&k,   g_k);
    cudaGetSymbolAddress((void**)&v,   g_v);
    cudaGetSymbolAddress((void**)&att, g_att);
    cudaGetSymbolAddress((void**)&ct,  g_ctab);
    cudaGetSymbolAddress((void**)&st,  g_stab);

    cudaFuncSetAttribute(flash_mma, cudaFuncAttributeMaxDynamicSharedMemorySize,
                         FLASH2_BYTES);

    build_tab<<<TSEQ, HD>>>(ct, st);

    gemm_mma<<<dim3(N_QKV/BN, M1/BM), 256>>>(x, w_qkv, qkv, M1, N_QKV, DIM);

    rope_split<<<dim3(NH, M1), HD>>>(qkv, ct, st, q, k, v);

    flash_mma<<<dim3(TSEQ/FQ, BATCH*NH), 256, FLASH2_BYTES>>>(q, k, v, att);

    gemm_mma<<<dim3(DIM/BN, M1/BM), 256>>>(att, w_proj, out, M1, DIM, DIM);
}

// round 6
// speedup vs baseline: 3.9496x; 1.5623x over previous
#include <cuda_runtime.h>
#include <cuda_bf16.h>
#include <math.h>
#include <stdint.h>

// Problem constants
#define BATCH 2
#define TSEQ  4096
#define DIM   2048
#define NH    16
#define HD    128
#define M1    (BATCH*TSEQ)      // 8192
#define N_QKV (3*DIM)           // 6144

// ---------------- scratch (static device globals; no allocs allowed) ----------
__device__ float g_qkv[(size_t)M1 * N_QKV];          // [8192,6144]
__device__ float g_q[(size_t)BATCH*NH*TSEQ*HD];
__device__ float g_k[(size_t)BATCH*NH*TSEQ*HD];
__device__ float g_v[(size_t)BATCH*NH*TSEQ*HD];
__device__ float g_att[(size_t)M1 * DIM];
__device__ float g_ctab[(size_t)TSEQ * HD];
__device__ float g_stab[(size_t)TSEQ * HD];
__device__ float g_xr[(size_t)M1 * DIM];             // tf32-rounded x
__device__ float g_wqkvr[(size_t)N_QKV * DIM];       // tf32-rounded w_qkv
__device__ float g_wprojr[(size_t)DIM * DIM];        // tf32-rounded w_proj

// ---------------- helpers -----------------------------------------------------
__device__ __forceinline__ uint32_t f2tf32(float x) {
    uint32_t u;
    asm("cvt.rna.tf32.f32 %0, %1;" : "=r"(u) : "f"(x));
    return u;
}

__device__ __forceinline__ void mma_tf32(float* d, const uint32_t* a, const uint32_t* b) {
    asm volatile(
        "mma.sync.aligned.m16n8k8.row.col.f32.tf32.tf32.f32 "
        "{%0,%1,%2,%3}, {%4,%5,%6,%7}, {%8,%9}, {%0,%1,%2,%3};"
        : "+f"(d[0]), "+f"(d[1]), "+f"(d[2]), "+f"(d[3])
        : "r"(a[0]), "r"(a[1]), "r"(a[2]), "r"(a[3]), "r"(b[0]), "r"(b[1]));
}

__device__ __forceinline__ uint32_t smem_u32(const void* p) {
    uint32_t a;
    asm("{ .reg .u64 t; cvta.to.shared.u64 t, %1; cvt.u32.u64 %0, t; }" : "=r"(a) : "l"(p));
    return a;
}
__device__ __forceinline__ void cp_async16(uint32_t saddr, const void* gaddr) {
    asm volatile("cp.async.cg.shared.global [%0], [%1], 16;" :: "r"(saddr), "l"(gaddr));
}
#define CP_COMMIT() asm volatile("cp.async.commit_group;" ::: "memory")
#define CP_WAIT1()  asm volatile("cp.async.wait_group 1;" ::: "memory")

// ---------------- cos/sin table ----------------------------------------------
__global__ void build_tab(float* __restrict__ ct, float* __restrict__ st) {
    int t = blockIdx.x;
    int j = threadIdx.x;
    int m = j & 63;
    float base = (float)pow(10000.0, (double)m / 64.0);
    float invf = 1.0f / base;
    float ang = (float)t * invf;
    ct[t*HD + j] = cosf(ang);
    st[t*HD + j] = sinf(ang);
}

// ---------------- tf32 pre-round pass ----------------------------------------
__global__ void round_tf32(const float* __restrict__ in, float* __restrict__ out) {
    size_t i = ((size_t)blockIdx.x * 256 + threadIdx.x) * 4;
    float4 v = *(const float4*)(in + i);
    float4 o;
    o.x = __uint_as_float(f2tf32(v.x)); o.y = __uint_as_float(f2tf32(v.y));
    o.z = __uint_as_float(f2tf32(v.z)); o.w = __uint_as_float(f2tf32(v.w));
    *(float4*)(out + i) = o;
}

// ---------------- cp.async pipelined tf32 GEMM: C = A * B^T -------------------
// 128x128 tile, BK=32, 3 stages, 256 threads (8 warps 2x4), warp tile 64x32.
#define BM 128
#define BN 128
#define BK2 32
#define STAGES 3
#define ASTR 36
#define GEMM2_SMEM (STAGES * (BM + BN) * ASTR * 4)   // 110592 B

__global__ __launch_bounds__(256, 2) void gemm_mma2(
    const float* __restrict__ A, const float* __restrict__ B,
    float* __restrict__ C, int M, int N, int K)
{
    extern __shared__ float smem[];
    uint32_t sbase = smem_u32(smem);
    const uint32_t boff = STAGES * BM * ASTR;   // B region offset (floats)

    int tid  = threadIdx.x;
    int wid  = tid >> 5, lane = tid & 31;
    int g    = lane >> 2, tg = lane & 3;
    int wm   = wid >> 2, wn = wid & 3;
    int m0   = blockIdx.y * BM;
    int n0   = blockIdx.x * BN;
    int lrow = tid >> 3;           // 0..31
    int lc4  = (tid & 7) << 2;     // 0..28

    float acc[4][4][4];
#pragma unroll
    for (int i = 0; i < 4; i++)
#pragma unroll
        for (int j = 0; j < 4; j++)
#pragma unroll
            for (int r = 0; r < 4; r++) acc[i][j][r] = 0.f;

    const int nch = K / BK2;

    auto issue = [&](int ch, int s, bool pred) {
        if (pred) {
            const float* Ag = A + (size_t)m0 * K + ch * BK2;
            const float* Bg = B + (size_t)n0 * K + ch * BK2;
            uint32_t as = sbase + (uint32_t)(s * BM * ASTR) * 4u;
            uint32_t bs = sbase + (boff + (uint32_t)(s * BN * ASTR)) * 4u;
#pragma unroll
            for (int e = 0; e < 4; e++) {
                int r = lrow + e * 32;
                cp_async16(as + (uint32_t)(r * ASTR + lc4) * 4u, Ag + (size_t)r * K + lc4);
                cp_async16(bs + (uint32_t)(r * ASTR + lc4) * 4u, Bg + (size_t)r * K + lc4);
            }
        }
        CP_COMMIT();
    };

    issue(0, 0, true);
    issue(1, 1, 1 < nch);

    for (int ch = 0; ch < nch; ch++) {
        CP_WAIT1();
        __syncthreads();
        issue(ch + 2, (ch + 2) % STAGES, ch + 2 < nch);

        int s = ch % STAGES;
        const float* asf = smem + s * BM * ASTR;
        const float* bsf = smem + boff + s * BN * ASTR;

#pragma unroll
        for (int ks = 0; ks < BK2; ks += 8) {
            uint32_t afr[4][4];
#pragma unroll
            for (int mi = 0; mi < 4; mi++) {
                int mr = wm * 64 + mi * 16;
                afr[mi][0] = __float_as_uint(asf[(mr + g    ) * ASTR + ks + tg]);
                afr[mi][1] = __float_as_uint(asf[(mr + g + 8) * ASTR + ks + tg]);
                afr[mi][2] = __float_as_uint(asf[(mr + g    ) * ASTR + ks + tg + 4]);
                afr[mi][3] = __float_as_uint(asf[(mr + g + 8) * ASTR + ks + tg + 4]);
            }
            uint32_t bfr[4][2];
#pragma unroll
            for (int nj = 0; nj < 4; nj++) {
                int nr = wn * 32 + nj * 8;
                bfr[nj][0] = __float_as_uint(bsf[(nr + g) * ASTR + ks + tg]);
                bfr[nj][1] = __float_as_uint(bsf[(nr + g) * ASTR + ks + tg + 4]);
            }
#pragma unroll
            for (int mi = 0; mi < 4; mi++)
#pragma unroll
                for (int nj = 0; nj < 4; nj++)
                    mma_tf32(acc[mi][nj], afr[mi], bfr[nj]);
        }
        __syncthreads();
    }

#pragma unroll
    for (int mi = 0; mi < 4; mi++) {
#pragma unroll
        for (int nj = 0; nj < 4; nj++) {
            int row = m0 + wm * 64 + mi * 16 + g;
            int col = n0 + wn * 32 + nj * 8 + tg * 2;
            *(float2*)(C + (size_t)row * N + col) =
                make_float2(acc[mi][nj][0], acc[mi][nj][1]);
            *(float2*)(C + (size_t)(row + 8) * N + col) =
                make_float2(acc[mi][nj][2], acc[mi][nj][3]);
        }
    }
}

// ---------------- RoPE + head split (outputs tf32-rounded) -------------------
__global__ void rope_split(const float* __restrict__ qkv,
                           const float* __restrict__ ct, const float* __restrict__ st,
                           float* __restrict__ Qo, float* __restrict__ Ko,
                           float* __restrict__ Vo)
{
    int h  = blockIdx.x;
    int bt = blockIdx.y;
    int j  = threadIdx.x;
    int b  = bt >> 12;
    int t  = bt & (TSEQ - 1);

    size_t base = (size_t)bt * N_QKV + h * HD;
    float c = ct[t*HD + j];
    float s = st[t*HD + j];

    float xq  = qkv[base + j];
    float xqp = qkv[base + (j ^ 1)];
    float rq  = (j & 1) ? xqp : -xqp;

    float xk  = qkv[base + DIM + j];
    float xkp = qkv[base + DIM + (j ^ 1)];
    float rk  = (j & 1) ? xkp : -xkp;

    float xv  = qkv[base + 2*DIM + j];

    size_t ob = ((size_t)(b*NH + h) * TSEQ + t) * HD + j;
    Qo[ob] = __uint_as_float(f2tf32(xq * c + rq * s));
    Ko[ob] = __uint_as_float(f2tf32(xk * c + rk * s));
    Vo[ob] = __uint_as_float(f2tf32(xv));
}

// ---------------- tf32 mma flash attention (causal) --------------------------
#define FQ 128
#define FK 64
#define QSTR 132
#define KSTR 132
#define VSTR 136
#define PSTR 68
#define OFF_Q 0
#define OFF_K (OFF_Q + FQ*QSTR)
#define OFF_V (OFF_K + FK*KSTR)
#define OFF_P (OFF_V + FK*VSTR)
#define FLASH2_FLOATS (OFF_P + FQ*PSTR)
#define FLASH2_BYTES (FLASH2_FLOATS * 4)

__global__ __launch_bounds__(256, 1) void flash_mma(
    const float* __restrict__ Q, const float* __restrict__ K,
    const float* __restrict__ V, float* __restrict__ Oatt)
{
    extern __shared__ float sm[];
    float* Qs = sm + OFF_Q;
    float* Ks = sm + OFF_K;
    float* Vs = sm + OFF_V;
    float* Ps = sm + OFF_P;

    int qi  = blockIdx.x;
    int bh  = blockIdx.y;
    int tid = threadIdx.x;
    int w    = tid >> 5;
    int lane = tid & 31;
    int g    = lane >> 2;
    int tg   = lane & 3;

    const float* Qp = Q + (size_t)bh * TSEQ * HD;
    const float* Kp = K + (size_t)bh * TSEQ * HD;
    const float* Vp = V + (size_t)bh * TSEQ * HD;

    int q0 = qi * FQ;

    // load Q tile (already tf32-rounded by rope_split)
#pragma unroll
    for (int e = 0; e < 16; e++) {
        int idx = tid + e * 256;
        int r  = idx >> 5;
        int c4 = (idx & 31) << 2;
        float4 v = *(const float4*)(Qp + (size_t)(q0 + r) * HD + c4);
        *(float4*)(Qs + r * QSTR + c4) = v;
    }

    float o[16][4];
#pragma unroll
    for (int i = 0; i < 16; i++)
#pragma unroll
        for (int j = 0; j < 4; j++) o[i][j] = 0.f;

    float m0r = -1e30f, m1r = -1e30f;
    float l0 = 0.f, l1 = 0.f;
    const float scale = 0.08838834764831845f;

    int rowbase = q0 + w * 16;
    int r0g = rowbase + g;
    int r1g = rowbase + g + 8;

    int nkt = 2 * qi + 2;
    for (int kt = 0; kt < nkt; kt++) {
        int k0 = kt * FK;
        __syncthreads();
#pragma unroll
        for (int e = 0; e < 8; e++) {
            int idx = tid + e * 256;
            int r  = idx >> 5;
            int c4 = (idx & 31) << 2;
            float4 kv = *(const float4*)(Kp + (size_t)(k0 + r) * HD + c4);
            *(float4*)(Ks + r * KSTR + c4) = kv;
            float4 vv = *(const float4*)(Vp + (size_t)(k0 + r) * HD + c4);
            *(float4*)(Vs + r * VSTR + c4) = vv;
        }
        __syncthreads();

        if (k0 > rowbase + 15) continue;

        float s[8][4];
#pragma unroll
        for (int nj = 0; nj < 8; nj++)
#pragma unroll
            for (int r = 0; r < 4; r++) s[nj][r] = 0.f;

#pragma unroll
        for (int ks = 0; ks < 16; ks++) {
            uint32_t a[4];
            a[0] = __float_as_uint(Qs[(rowbase - q0 + g    ) * QSTR + ks*8 + tg]);
            a[1] = __float_as_uint(Qs[(rowbase - q0 + g + 8) * QSTR + ks*8 + tg]);
            a[2] = __float_as_uint(Qs[(rowbase - q0 + g    ) * QSTR + ks*8 + tg + 4]);
            a[3] = __float_as_uint(Qs[(rowbase - q0 + g + 8) * QSTR + ks*8 + tg + 4]);
#pragma unroll
            for (int nj = 0; nj < 8; nj++) {
                uint32_t b[2];
                b[0] = __float_as_uint(Ks[(nj*8 + g) * KSTR + ks*8 + tg]);
                b[1] = __float_as_uint(Ks[(nj*8 + g) * KSTR + ks*8 + tg + 4]);
                mma_tf32(s[nj], a, b);
            }
        }

        if (k0 + FK - 1 > rowbase) {
#pragma unroll
            for (int nj = 0; nj < 8; nj++) {
                int c = k0 + nj*8 + 2*tg;
                if (c     > r0g) s[nj][0] = -1e30f;
                if (c + 1 > r0g) s[nj][1] = -1e30f;
                if (c     > r1g) s[nj][2] = -1e30f;
                if (c + 1 > r1g) s[nj][3] = -1e30f;
            }
        }

        float mx0 = -1e30f, mx1 = -1e30f;
#pragma unroll
        for (int nj = 0; nj < 8; nj++) {
            mx0 = fmaxf(mx0, fmaxf(s[nj][0], s[nj][1]));
            mx1 = fmaxf(mx1, fmaxf(s[nj][2], s[nj][3]));
        }
        mx0 = fmaxf(mx0, __shfl_xor_sync(0xffffffff, mx0, 1));
        mx0 = fmaxf(mx0, __shfl_xor_sync(0xffffffff, mx0, 2));
        mx1 = fmaxf(mx1, __shfl_xor_sync(0xffffffff, mx1, 1));
        mx1 = fmaxf(mx1, __shfl_xor_sync(0xffffffff, mx1, 2));

        float mn0 = fmaxf(m0r, mx0);
        float mn1 = fmaxf(m1r, mx1);
        float al0 = __expf((m0r - mn0) * scale);
        float al1 = __expf((m1r - mn1) * scale);
        m0r = mn0; m1r = mn1;

        float sum0 = 0.f, sum1 = 0.f;
#pragma unroll
        for (int nj = 0; nj < 8; nj++) {
            float p0 = __expf((s[nj][0] - mn0) * scale);
            float p1 = __expf((s[nj][1] - mn0) * scale);
            float p2 = __expf((s[nj][2] - mn1) * scale);
            float p3 = __expf((s[nj][3] - mn1) * scale);
            s[nj][0] = p0; s[nj][1] = p1; s[nj][2] = p2; s[nj][3] = p3;
            sum0 += p0 + p1; sum1 += p2 + p3;
        }
        sum0 += __shfl_xor_sync(0xffffffff, sum0, 1);
        sum0 += __shfl_xor_sync(0xffffffff, sum0, 2);
        sum1 += __shfl_xor_sync(0xffffffff, sum1, 1);
        sum1 += __shfl_xor_sync(0xffffffff, sum1, 2);

        l0 = l0 * al0 + sum0;
        l1 = l1 * al1 + sum1;

#pragma unroll
        for (int t2 = 0; t2 < 16; t2++) {
            o[t2][0] *= al0; o[t2][1] *= al0;
            o[t2][2] *= al1; o[t2][3] *= al1;
        }

        int pr0 = (rowbase - q0 + g) * PSTR;
        int pr1 = (rowbase - q0 + g + 8) * PSTR;
#pragma unroll
        for (int nj = 0; nj < 8; nj++) {
            int c = nj*8 + 2*tg;
            Ps[pr0 + c    ] = __uint_as_float(f2tf32(s[nj][0]));
            Ps[pr0 + c + 1] = __uint_as_float(f2tf32(s[nj][1]));
            Ps[pr1 + c    ] = __uint_as_float(f2tf32(s[nj][2]));
            Ps[pr1 + c + 1] = __uint_as_float(f2tf32(s[nj][3]));
        }
        __syncwarp();

#pragma unroll
        for (int ks2 = 0; ks2 < 8; ks2++) {
            uint32_t a2[4];
            a2[0] = __float_as_uint(Ps[pr0 + ks2*8 + tg]);
            a2[1] = __float_as_uint(Ps[pr1 + ks2*8 + tg]);
            a2[2] = __float_as_uint(Ps[pr0 + ks2*8 + tg + 4]);
            a2[3] = __float_as_uint(Ps[pr1 + ks2*8 + tg + 4]);
#pragma unroll
            for (int nj2 = 0; nj2 < 16; nj2++) {
                uint32_t b2[2];
                b2[0] = __float_as_uint(Vs[(ks2*8 + tg    ) * VSTR + nj2*8 + g]);
                b2[1] = __float_as_uint(Vs[(ks2*8 + tg + 4) * VSTR + nj2*8 + g]);
                mma_tf32(o[nj2], a2, b2);
            }
        }
        __syncwarp();
    }

    // epilogue: normalize + tf32-round (proj GEMM A operand) + write
    float inv0 = 1.0f / l0;
    float inv1 = 1.0f / l1;
    int b = bh >> 4, h = bh & 15;
#pragma unroll
    for (int nj2 = 0; nj2 < 16; nj2++) {
        int col = h * HD + nj2*8 + 2*tg;
        *(float2*)(Oatt + (size_t)(b*TSEQ + r0g) * DIM + col) =
            make_float2(__uint_as_float(f2tf32(o[nj2][0] * inv0)),
                        __uint_as_float(f2tf32(o[nj2][1] * inv0)));
        *(float2*)(Oatt + (size_t)(b*TSEQ + r1g) * DIM + col) =
            make_float2(__uint_as_float(f2tf32(o[nj2][2] * inv1)),
                        __uint_as_float(f2tf32(o[nj2][3] * inv1)));
    }
}

// ---------------- launch ------------------------------------------------------
extern "C" void kernel_launch(void* const* d_in, const int* in_sizes, int n_in,
                              void* d_out, int out_size) {
    const float* x      = (const float*)d_in[0];
    const float* w_qkv  = (const float*)d_in[1];
    const float* w_proj = (const float*)d_in[2];
    float* out = (float*)d_out;

    float *qkv, *q, *k, *v, *att, *ct, *st, *xr, *wqkvr, *wprojr;
    cudaGetSymbolAddress((void**)&qkv,    g_qkv);
    cudaGetSymbolAddress((void**)&q,      g_q);
    cudaGetSymbolAddress((void**)&k,      g_k);
    cudaGetSymbolAddress((void**)&v,      g_v);
    cudaGetSymbolAddress((void**)&att,    g_att);
    cudaGetSymbolAddress((void**)&ct,     g_ctab);
    cudaGetSymbolAddress((void**)&st,     g_stab);
    cudaGetSymbolAddress((void**)&xr,     g_xr);
    cudaGetSymbolAddress((void**)&wqkvr,  g_wqkvr);
    cudaGetSymbolAddress((void**)&wprojr, g_wprojr);

    cudaFuncSetAttribute(gemm_mma2, cudaFuncAttributeMaxDynamicSharedMemorySize, GEMM2_SMEM);
    cudaFuncSetAttribute(flash_mma, cudaFuncAttributeMaxDynamicSharedMemorySize, FLASH2_BYTES);

    build_tab<<<TSEQ, HD>>>(ct, st);

    round_tf32<<<(M1*(size_t)DIM)/(256*4), 256>>>(x, xr);
    round_tf32<<<((size_t)N_QKV*DIM)/(256*4), 256>>>(w_qkv, wqkvr);
    round_tf32<<<((size_t)DIM*DIM)/(256*4), 256>>>(w_proj, wprojr);

    gemm_mma2<<<dim3(N_QKV/BN, M1/BM), 256, GEMM2_SMEM>>>(xr, wqkvr, qkv, M1, N_QKV, DIM);

    rope_split<<<dim3(NH, M1), HD>>>(qkv, ct, st, q, k, v);

    flash_mma<<<dim3(TSEQ/FQ, BATCH*NH), 256, FLASH2_BYTES>>>(q, k, v, att);

    gemm_mma2<<<dim3(DIM/BN, M1/BM), 256, GEMM2_SMEM>>>(att, wprojr, out, M1, DIM, DIM);
}